// round 11
// baseline (speedup 1.0000x reference)
#include <cuda_runtime.h>
#include <cuda_bf16.h>
#include <mma.h>
#include <math.h>
#include <stdint.h>

using namespace nvcuda;

// ---------------- problem constants ----------------
#define BATCH   8192
#define TSTEPS  99
#define DIN     32
#define DH      100
#define RW      16
#define RU      25
#define NCLS    6
#define MROWS   64
#define NBLK    (BATCH / MROWS)      // 128
#define NTHR    448                  // 14 warps: warp grid 2(m) x 7(n)

// A: 64 x 296 bf16. cols: 0-111 Hhi, 112-223 Hlo, 224-255 xhi, 256-287 xlo
#define A_LD    296
#define A_BYTES (64 * A_LD * 2)
// B: 288 x 136 bf16. rows: 0-111 Uhi, 112-223 Ulo, 224-255 Whi, 256-287 Wlo
#define B_LD    136
#define B_BYTES (288 * B_LD * 2)
// C: 64 x 132 fp32
#define C_LD    132
#define C_BYTES (64 * C_LD * 4)

#define SM_A    0
#define SM_B    (SM_A + A_BYTES)
#define SM_C    (SM_B + B_BYTES)
#define SM_BB   (SM_C + C_BYTES)
#define SM_TOT  (SM_BB + 1024)       // 151040 B

// ---------------- device-global prepped data ----------------
__device__ __align__(16) __nv_bfloat16 g_Bs[288 * B_LD];
__device__ float g_bb[224];
__device__ float g_sc[2];
__device__ __align__(16) __nv_bfloat16 g_AXB[(size_t)NBLK * TSTEPS * 4096];

__device__ __forceinline__ float tanha(float v) {
    float r; asm("tanh.approx.f32 %0, %1;" : "=f"(r) : "f"(v)); return r;
}
__device__ __forceinline__ uint32_t pk2(__nv_bfloat16 a, __nv_bfloat16 b) {
    return (uint32_t)__bfloat16_as_ushort(a) | ((uint32_t)__bfloat16_as_ushort(b) << 16);
}

// ---------------- setup 1: weights -> split B image (r10 verbatim) ----------------
__global__ void setup_w(const float* __restrict__ W1, const float* __restrict__ W2,
                        const float* __restrict__ U1, const float* __restrict__ U2,
                        const float* __restrict__ bg, const float* __restrict__ bu,
                        const float* __restrict__ zeta, const float* __restrict__ nu) {
    int tid = blockIdx.x * blockDim.x + threadIdx.x;
    int nth = gridDim.x * blockDim.x;
    for (int idx = tid; idx < 288 * B_LD; idx += nth) {
        int k = idx / B_LD, n = idx % B_LD;
        float v = 0.f;
        bool lo = false;
        if (n < DH) {
            if (k < 112) {
                if (k < DH)
                    for (int r = 0; r < RU; r++) v = fmaf(U1[k * RU + r], U2[r * DH + n], v);
            } else if (k < 224) {
                int kk = k - 112; lo = true;
                if (kk < DH)
                    for (int r = 0; r < RU; r++) v = fmaf(U1[kk * RU + r], U2[r * DH + n], v);
            } else if (k < 256) {
                int kk = k - 224;
                for (int r = 0; r < RW; r++) v = fmaf(W1[kk * RW + r], W2[r * DH + n], v);
            } else {
                int kk = k - 256; lo = true;
                for (int r = 0; r < RW; r++) v = fmaf(W1[kk * RW + r], W2[r * DH + n], v);
            }
        }
        __nv_bfloat16 hi = __float2bfloat16_rn(v);
        g_Bs[idx] = lo ? __float2bfloat16_rn(v - __bfloat162float(hi)) : hi;
    }
    for (int j = tid; j < 112; j += nth) {
        g_bb[2 * j]     = (j < DH) ? bg[j] : 0.f;
        g_bb[2 * j + 1] = (j < DH) ? bu[j] : 0.f;
    }
    if (tid == 0) {
        g_sc[0] = 1.f / (1.f + expf(-zeta[0]));
        g_sc[1] = 1.f / (1.f + expf(-nu[0]));
    }
}

// ---------------- setup 2: x -> split hi/lo row images (r10 verbatim) ----------------
__global__ void __launch_bounds__(256)
setup_x(const float* __restrict__ x) {
    int gid = blockIdx.x * 256 + threadIdx.x;
    int blk = gid / (TSTEPS * MROWS);
    int rem = gid % (TSTEPS * MROWS);
    int t = rem / MROWS, r = rem % MROWS;
    const float* xr = x + (size_t)(blk * MROWS + r) * (TSTEPS * DIN) + t * DIN;
    __nv_bfloat16 buf[64];
#pragma unroll
    for (int k = 0; k < DIN; k++) {
        float v = xr[k];
        __nv_bfloat16 hi = __float2bfloat16_rn(v);
        buf[k]      = hi;
        buf[32 + k] = __float2bfloat16_rn(v - __bfloat162float(hi));
    }
    uint4* dst = (uint4*)(g_AXB + ((size_t)(blk * TSTEPS + t)) * 4096 + r * 64);
    const uint4* src = (const uint4*)buf;
#pragma unroll
    for (int i = 0; i < 8; i++) dst[i] = src[i];
}

// ---------------- persistent WMMA recurrent kernel (14 warps) ----------------
__global__ void __launch_bounds__(NTHR)
grnn_kernel(const float* __restrict__ FC, const float* __restrict__ FCb,
            float* __restrict__ out) {
    extern __shared__ __align__(16) char sm[];
    __nv_bfloat16* As = (__nv_bfloat16*)(sm + SM_A);
    __nv_bfloat16* Bs = (__nv_bfloat16*)(sm + SM_B);
    float*  Cs  = (float*)(sm + SM_C);
    float2* bbs = (float2*)(sm + SM_BB);

    const int tid = threadIdx.x;
    const int blk = blockIdx.x;

    // ---- init ----
    {
        uint4* d = (uint4*)Bs; const uint4* s = (const uint4*)g_Bs;
        for (int i = tid; i < B_BYTES / 16; i += NTHR) d[i] = s[i];
        d = (uint4*)As;
        for (int i = tid; i < A_BYTES / 16; i += NTHR) d[i] = make_uint4(0, 0, 0, 0);
        const uint4* xs0 = (const uint4*)(g_AXB + (size_t)blk * TSTEPS * 4096);
        for (int i = tid; i < 512; i += NTHR)
            *(uint4*)((char*)As + (i >> 3) * (A_LD * 2) + 448 + (i & 7) * 16) = xs0[i];
        for (int j = tid; j < 112; j += NTHR)
            bbs[j] = make_float2(g_bb[2 * j], g_bb[2 * j + 1]);
    }
    __syncthreads();

    const float sz = g_sc[0];
    const float sn = g_sc[1];

    const int w   = tid >> 5;
    const int mi2 = w & 1;                // row half: rows 32*mi2 .. +31
    const int nj  = w >> 1;               // n-tile: cols 16*nj .. +15 (0..6)

    // epilogue mapping: 448 = 64 rows x 7 col-groups of 16
    const int erow  = tid / 7;
    const int ecg   = tid % 7;
    const int ecol0 = ecg * 16;

    // hoisted per-thread biases (fixed cols)
    float2 bbv[16];
#pragma unroll
    for (int i = 0; i < 16; i++) bbv[i] = bbs[ecol0 + i];

    float H[16];
#pragma unroll
    for (int i = 0; i < 16; i++) H[i] = 0.f;

    wmma::fragment<wmma::accumulator, 16, 16, 16, float> cf[2];
    wmma::fragment<wmma::matrix_a, 16, 16, 16, __nv_bfloat16, wmma::row_major> ah[2], al[2];
    wmma::fragment<wmma::matrix_b, 16, 16, 16, __nv_bfloat16, wmma::row_major> bh, bl;

    const bool xtra = (tid < 64);         // handles second x chunk (512 = 448 + 64)

    for (int t = 0; t < TSTEPS; t++) {
        // prefetch next step's x rows
        uint4 xp0, xp1;
        const int hx = (t + 1 < TSTEPS);
        if (hx) {
            const uint4* s = (const uint4*)(g_AXB + (size_t)(blk * TSTEPS + t + 1) * 4096);
            xp0 = s[tid];
            if (xtra) xp1 = s[tid + NTHR];
        }

        // ---- MMA phase ----
        wmma::fill_fragment(cf[0], 0.f);
        wmma::fill_fragment(cf[1], 0.f);

        // U part (7 k-units)
#pragma unroll
        for (int kk = 0; kk < 7; kk++) {
#pragma unroll
            for (int mi = 0; mi < 2; mi++) {
                const __nv_bfloat16* ar = As + (32 * mi2 + 16 * mi) * A_LD + 16 * kk;
                wmma::load_matrix_sync(ah[mi], ar, A_LD);
                wmma::load_matrix_sync(al[mi], ar + 112, A_LD);
            }
            const __nv_bfloat16* br = Bs + (16 * kk) * B_LD + 16 * nj;
            wmma::load_matrix_sync(bh, br, B_LD);
            wmma::load_matrix_sync(bl, br + 112 * B_LD, B_LD);
#pragma unroll
            for (int mi = 0; mi < 2; mi++) {
                wmma::mma_sync(cf[mi], ah[mi], bh, cf[mi]);
                wmma::mma_sync(cf[mi], al[mi], bh, cf[mi]);
                wmma::mma_sync(cf[mi], ah[mi], bl, cf[mi]);
            }
        }
        // x part (2 k-units)
#pragma unroll
        for (int kk = 0; kk < 2; kk++) {
#pragma unroll
            for (int mi = 0; mi < 2; mi++) {
                const __nv_bfloat16* ar = As + (32 * mi2 + 16 * mi) * A_LD + 224 + 16 * kk;
                wmma::load_matrix_sync(ah[mi], ar, A_LD);
                wmma::load_matrix_sync(al[mi], ar + 32, A_LD);
            }
            const __nv_bfloat16* br = Bs + (224 + 16 * kk) * B_LD + 16 * nj;
            wmma::load_matrix_sync(bh, br, B_LD);
            wmma::load_matrix_sync(bl, br + 32 * B_LD, B_LD);
#pragma unroll
            for (int mi = 0; mi < 2; mi++) {
                wmma::mma_sync(cf[mi], ah[mi], bh, cf[mi]);
                wmma::mma_sync(cf[mi], al[mi], bh, cf[mi]);
                wmma::mma_sync(cf[mi], ah[mi], bl, cf[mi]);
            }
        }
#pragma unroll
        for (int mi = 0; mi < 2; mi++)
            wmma::store_matrix_sync(Cs + (32 * mi2 + 16 * mi) * C_LD + 16 * nj,
                                    cf[mi], C_LD, wmma::mem_row_major);
        __syncthreads();

        // ---- epilogue: 16 elements per thread ----
        const float* crow = Cs + erow * C_LD + ecol0;
        float cc[16];
#pragma unroll
        for (int i4 = 0; i4 < 4; i4++) {
            float4 v = *(const float4*)(crow + 4 * i4);
            cc[4 * i4] = v.x; cc[4 * i4 + 1] = v.y; cc[4 * i4 + 2] = v.z; cc[4 * i4 + 3] = v.w;
        }
#pragma unroll
        for (int i = 0; i < 16; i++) {
            float2 bb = bbv[i];
            float gg = fmaf(0.5f, tanha(0.5f * (cc[i] + bb.x)), 0.5f);
            float hh = tanha(cc[i] + bb.y);
            H[i] = fmaf(gg, H[i] - sz, fmaf(sn, hh, sz));
        }
        char* arow = (char*)As + erow * (A_LD * 2);
#pragma unroll
        for (int i2 = 0; i2 < 8; i2++) {
            float h0 = H[2 * i2], h1 = H[2 * i2 + 1];
            __nv_bfloat16 h0h = __float2bfloat16_rn(h0);
            __nv_bfloat16 h1h = __float2bfloat16_rn(h1);
            __nv_bfloat16 h0l = __float2bfloat16_rn(h0 - __bfloat162float(h0h));
            __nv_bfloat16 h1l = __float2bfloat16_rn(h1 - __bfloat162float(h1h));
            *(uint32_t*)(arow + (ecol0 + 2 * i2) * 2)       = pk2(h0h, h1h);
            *(uint32_t*)(arow + (112 + ecol0 + 2 * i2) * 2) = pk2(h0l, h1l);
        }
        if (hx) {
            *(uint4*)((char*)As + (tid >> 3) * (A_LD * 2) + 448 + (tid & 7) * 16) = xp0;
            if (xtra) {
                int i = tid + NTHR;
                *(uint4*)((char*)As + (i >> 3) * (A_LD * 2) + 448 + (i & 7) * 16) = xp1;
            }
        }
        __syncthreads();
    }

    // ---- scores: per-thread partial over 16 cols, smem-atomic reduce (reuse Cs) ----
    float* scr = Cs;
    for (int i = tid; i < MROWS * NCLS; i += NTHR) scr[i] = 0.f;
    __syncthreads();
    {
        float s[NCLS];
#pragma unroll
        for (int c = 0; c < NCLS; c++) s[c] = 0.f;
#pragma unroll
        for (int i = 0; i < 16; i++) {
            int j = ecol0 + i;
            if (j < DH) {
                float hv = H[i];
#pragma unroll
                for (int c = 0; c < NCLS; c++)
                    s[c] = fmaf(hv, __ldg(FC + j * NCLS + c), s[c]);
            }
        }
#pragma unroll
        for (int c = 0; c < NCLS; c++)
            atomicAdd(&scr[erow * NCLS + c], s[c]);
    }
    __syncthreads();
    if (tid < MROWS) {
        int grow = blk * MROWS + tid;
#pragma unroll
        for (int c = 0; c < NCLS; c++)
            out[(size_t)grow * NCLS + c] = scr[tid * NCLS + c] + __ldg(FCb + c);
    }
}

// ---------------- launch ----------------
extern "C" void kernel_launch(void* const* d_in, const int* in_sizes, int n_in,
                              void* d_out, int out_size) {
    const float* x    = (const float*)d_in[0];
    const float* W1   = (const float*)d_in[1];
    const float* W2   = (const float*)d_in[2];
    const float* U1   = (const float*)d_in[3];
    const float* U2   = (const float*)d_in[4];
    const float* bg   = (const float*)d_in[5];
    const float* bu   = (const float*)d_in[6];
    const float* zeta = (const float*)d_in[7];
    const float* nu   = (const float*)d_in[8];
    const float* FC   = (const float*)d_in[9];
    const float* FCb  = (const float*)d_in[10];
    float* out = (float*)d_out;

    cudaFuncSetAttribute(grnn_kernel, cudaFuncAttributeMaxDynamicSharedMemorySize, SM_TOT);

    setup_w<<<16, 256>>>(W1, W2, U1, U2, bg, bu, zeta, nu);
    setup_x<<<(NBLK * TSTEPS * MROWS) / 256, 256>>>(x);
    grnn_kernel<<<NBLK, NTHR, SM_TOT>>>(FC, FCb, out);
}

// round 12
// speedup vs baseline: 1.4891x; 1.4891x over previous
#include <cuda_runtime.h>
#include <cuda_bf16.h>
#include <math.h>
#include <stdint.h>

// ---------------- problem constants ----------------
#define BATCH   8192
#define TSTEPS  99
#define DIN     32
#define DH      100
#define RW      16
#define RU      25
#define NCLS    6
#define MROWS   64
#define NBLK    (BATCH / MROWS)      // 128
#define NTHR    448                  // 14 warps: 2(m) x 7(n)

// A: 64 x 296 bf16. cols: 0-111 Hhi, 112-223 Hlo, 224-255 xhi, 256-287 xlo
#define A_LD    296
#define A_BYTES (64 * A_LD * 2)
// B: 288 x 136 bf16. rows: 0-111 Uhi, 112-223 Ulo, 224-255 Whi, 256-287 Wlo
#define B_LD    136
#define B_BYTES (288 * B_LD * 2)

#define SM_A    0
#define SM_B    (SM_A + A_BYTES)
#define SM_BB   (SM_B + B_BYTES)
#define SM_SCR  (SM_BB + 1024)
#define SM_TOT  (SM_SCR + 1536)     // 118784 B

// ---------------- device-global prepped data ----------------
__device__ __align__(16) __nv_bfloat16 g_Bs[288 * B_LD];
__device__ float g_bb[224];
__device__ float g_sc[2];
__device__ __align__(16) __nv_bfloat16 g_AXB[(size_t)NBLK * TSTEPS * 4096];

__device__ __forceinline__ float tanha(float v) {
    float r; asm("tanh.approx.f32 %0, %1;" : "=f"(r) : "f"(v)); return r;
}
__device__ __forceinline__ uint32_t pk2(__nv_bfloat16 a, __nv_bfloat16 b) {
    return (uint32_t)__bfloat16_as_ushort(a) | ((uint32_t)__bfloat16_as_ushort(b) << 16);
}
__device__ __forceinline__ uint32_t bfsplit(float v0, float v1, uint32_t& lo) {
    __nv_bfloat16 h0 = __float2bfloat16_rn(v0);
    __nv_bfloat16 h1 = __float2bfloat16_rn(v1);
    lo = pk2(__float2bfloat16_rn(v0 - __bfloat162float(h0)),
             __float2bfloat16_rn(v1 - __bfloat162float(h1)));
    return pk2(h0, h1);
}

#define LDSM4(r0,r1,r2,r3,a) \
    asm volatile("ldmatrix.sync.aligned.m8n8.x4.shared.b16 {%0,%1,%2,%3}, [%4];" \
                 : "=r"(r0),"=r"(r1),"=r"(r2),"=r"(r3) : "r"(a))
#define LDSM4T(r0,r1,r2,r3,a) \
    asm volatile("ldmatrix.sync.aligned.m8n8.x4.trans.shared.b16 {%0,%1,%2,%3}, [%4];" \
                 : "=r"(r0),"=r"(r1),"=r"(r2),"=r"(r3) : "r"(a))
#define MMA(c0,c1,c2,c3,a0,a1,a2,a3,b0,b1) \
    asm volatile("mma.sync.aligned.m16n8k16.row.col.f32.bf16.bf16.f32 " \
                 "{%0,%1,%2,%3}, {%4,%5,%6,%7}, {%8,%9}, {%0,%1,%2,%3};" \
                 : "+f"(c0),"+f"(c1),"+f"(c2),"+f"(c3) \
                 : "r"(a0),"r"(a1),"r"(a2),"r"(a3),"r"(b0),"r"(b1))

// ---------------- setup 1: weights -> split B image (r10 verbatim) ----------------
__global__ void setup_w(const float* __restrict__ W1, const float* __restrict__ W2,
                        const float* __restrict__ U1, const float* __restrict__ U2,
                        const float* __restrict__ bg, const float* __restrict__ bu,
                        const float* __restrict__ zeta, const float* __restrict__ nu) {
    int tid = blockIdx.x * blockDim.x + threadIdx.x;
    int nth = gridDim.x * blockDim.x;
    for (int idx = tid; idx < 288 * B_LD; idx += nth) {
        int k = idx / B_LD, n = idx % B_LD;
        float v = 0.f;
        bool lo = false;
        if (n < DH) {
            if (k < 112) {
                if (k < DH)
                    for (int r = 0; r < RU; r++) v = fmaf(U1[k * RU + r], U2[r * DH + n], v);
            } else if (k < 224) {
                int kk = k - 112; lo = true;
                if (kk < DH)
                    for (int r = 0; r < RU; r++) v = fmaf(U1[kk * RU + r], U2[r * DH + n], v);
            } else if (k < 256) {
                int kk = k - 224;
                for (int r = 0; r < RW; r++) v = fmaf(W1[kk * RW + r], W2[r * DH + n], v);
            } else {
                int kk = k - 256; lo = true;
                for (int r = 0; r < RW; r++) v = fmaf(W1[kk * RW + r], W2[r * DH + n], v);
            }
        }
        __nv_bfloat16 hi = __float2bfloat16_rn(v);
        g_Bs[idx] = lo ? __float2bfloat16_rn(v - __bfloat162float(hi)) : hi;
    }
    for (int j = tid; j < 112; j += nth) {
        g_bb[2 * j]     = (j < DH) ? bg[j] : 0.f;
        g_bb[2 * j + 1] = (j < DH) ? bu[j] : 0.f;
    }
    if (tid == 0) {
        g_sc[0] = 1.f / (1.f + expf(-zeta[0]));
        g_sc[1] = 1.f / (1.f + expf(-nu[0]));
    }
}

// ---------------- setup 2: x -> split hi/lo row images (r10 verbatim) ----------------
__global__ void __launch_bounds__(256)
setup_x(const float* __restrict__ x) {
    int gid = blockIdx.x * 256 + threadIdx.x;
    int blk = gid / (TSTEPS * MROWS);
    int rem = gid % (TSTEPS * MROWS);
    int t = rem / MROWS, r = rem % MROWS;
    const float* xr = x + (size_t)(blk * MROWS + r) * (TSTEPS * DIN) + t * DIN;
    __nv_bfloat16 buf[64];
#pragma unroll
    for (int k = 0; k < DIN; k++) {
        float v = xr[k];
        __nv_bfloat16 hi = __float2bfloat16_rn(v);
        buf[k]      = hi;
        buf[32 + k] = __float2bfloat16_rn(v - __bfloat162float(hi));
    }
    uint4* dst = (uint4*)(g_AXB + ((size_t)(blk * TSTEPS + t)) * 4096 + r * 64);
    const uint4* src = (const uint4*)buf;
#pragma unroll
    for (int i = 0; i < 8; i++) dst[i] = src[i];
}

// ---------------- persistent raw-MMA recurrent kernel ----------------
__global__ void __launch_bounds__(NTHR)
grnn_kernel(const float* __restrict__ FC, const float* __restrict__ FCb,
            float* __restrict__ out) {
    extern __shared__ __align__(16) char sm[];
    __nv_bfloat16* As = (__nv_bfloat16*)(sm + SM_A);
    __nv_bfloat16* Bs = (__nv_bfloat16*)(sm + SM_B);
    float2* bbs = (float2*)(sm + SM_BB);
    float*  scr = (float*)(sm + SM_SCR);

    const int tid = threadIdx.x;
    const int blk = blockIdx.x;

    // ---- init ----
    {
        uint4* d = (uint4*)Bs; const uint4* s = (const uint4*)g_Bs;
        for (int i = tid; i < B_BYTES / 16; i += NTHR) d[i] = s[i];
        d = (uint4*)As;
        for (int i = tid; i < A_BYTES / 16; i += NTHR) d[i] = make_uint4(0, 0, 0, 0);
        const uint4* xs0 = (const uint4*)(g_AXB + (size_t)blk * TSTEPS * 4096);
        for (int i = tid; i < 512; i += NTHR)
            *(uint4*)((char*)As + (i >> 3) * (A_LD * 2) + 448 + (i & 7) * 16) = xs0[i];
        for (int j = tid; j < 112; j += NTHR)
            bbs[j] = make_float2(g_bb[2 * j], g_bb[2 * j + 1]);
    }
    __syncthreads();

    const float sz = g_sc[0];
    const float sn = g_sc[1];

    const int w    = tid >> 5;
    const int lane = tid & 31;
    const int wm   = w & 1;              // row half: rows 32*wm .. +31
    const int wn   = w >> 1;             // n16 block: cols 16*wn .. +15
    const int g    = lane >> 2;
    const int tg   = lane & 3;
    const int lm   = lane >> 3;          // ldmatrix matrix id
    const int lr   = lane & 7;

    // ldmatrix per-lane base addresses
    uint32_t As32 = (uint32_t)__cvta_generic_to_shared(As);
    uint32_t Bs32 = (uint32_t)__cvta_generic_to_shared(Bs);
    uint32_t aAddr0 = As32 + (uint32_t)(((32 * wm + lr + ((lm & 1) << 3)) * A_LD + ((lm >> 1) << 3)) * 2);
    uint32_t aAddr1 = aAddr0 + 16 * A_LD * 2;
    uint32_t bAddr  = Bs32 + (uint32_t)(((lr + ((lm & 1) << 3)) * B_LD + 16 * wn + ((lm >> 1) << 3)) * 2);

    // hoisted per-thread biases: cols C(ni,e) = 16wn + 8ni + 2tg + e
    float bgv[2][2], buv[2][2];
#pragma unroll
    for (int ni = 0; ni < 2; ni++)
#pragma unroll
        for (int e = 0; e < 2; e++) {
            float2 bb = bbs[16 * wn + 8 * ni + 2 * tg + e];
            bgv[ni][e] = bb.x; buv[ni][e] = bb.y;
        }

    float H[2][2][4];   // [mi][ni][c-frag], rows {g,g+8}+16mi+32wm, cols 2tg,2tg+1 +8ni+16wn
#pragma unroll
    for (int mi = 0; mi < 2; mi++)
#pragma unroll
        for (int ni = 0; ni < 2; ni++)
#pragma unroll
            for (int e = 0; e < 4; e++) H[mi][ni][e] = 0.f;

    for (int t = 0; t < TSTEPS; t++) {
        // prefetch next step's x rows
        uint4 xp0, xp1;
        const int hx = (t + 1 < TSTEPS);
        if (hx) {
            const uint4* s = (const uint4*)(g_AXB + (size_t)(blk * TSTEPS + t + 1) * 4096);
            xp0 = s[tid];
            if (tid < 64) xp1 = s[tid + NTHR];
        }

        float c[2][2][4];
#pragma unroll
        for (int mi = 0; mi < 2; mi++)
#pragma unroll
            for (int ni = 0; ni < 2; ni++)
#pragma unroll
                for (int e = 0; e < 4; e++) c[mi][ni][e] = 0.f;

        // ---- H part: 7 k-units ----
#pragma unroll
        for (int kk = 0; kk < 7; kk++) {
            uint32_t bh0, bh1, bh2, bh3, bl0, bl1, bl2, bl3;
            uint32_t kb = bAddr + kk * 16 * B_LD * 2;
            LDSM4T(bh0, bh1, bh2, bh3, kb);
            LDSM4T(bl0, bl1, bl2, bl3, kb + 112 * B_LD * 2);
#pragma unroll
            for (int mi = 0; mi < 2; mi++) {
                uint32_t ka = (mi ? aAddr1 : aAddr0) + kk * 32;
                uint32_t a0, a1, a2, a3, l0, l1, l2, l3;
                LDSM4(a0, a1, a2, a3, ka);
                LDSM4(l0, l1, l2, l3, ka + 224);
                MMA(c[mi][0][0], c[mi][0][1], c[mi][0][2], c[mi][0][3], a0, a1, a2, a3, bh0, bh1);
                MMA(c[mi][1][0], c[mi][1][1], c[mi][1][2], c[mi][1][3], a0, a1, a2, a3, bh2, bh3);
                MMA(c[mi][0][0], c[mi][0][1], c[mi][0][2], c[mi][0][3], l0, l1, l2, l3, bh0, bh1);
                MMA(c[mi][1][0], c[mi][1][1], c[mi][1][2], c[mi][1][3], l0, l1, l2, l3, bh2, bh3);
                MMA(c[mi][0][0], c[mi][0][1], c[mi][0][2], c[mi][0][3], a0, a1, a2, a3, bl0, bl1);
                MMA(c[mi][1][0], c[mi][1][1], c[mi][1][2], c[mi][1][3], a0, a1, a2, a3, bl2, bl3);
            }
        }
        // ---- x part: 2 k-units ----
#pragma unroll
        for (int kk = 0; kk < 2; kk++) {
            uint32_t bh0, bh1, bh2, bh3, bl0, bl1, bl2, bl3;
            uint32_t kb = bAddr + (224 + 16 * kk) * B_LD * 2;
            LDSM4T(bh0, bh1, bh2, bh3, kb);
            LDSM4T(bl0, bl1, bl2, bl3, kb + 32 * B_LD * 2);
#pragma unroll
            for (int mi = 0; mi < 2; mi++) {
                uint32_t ka = (mi ? aAddr1 : aAddr0) + (224 + 16 * kk) * 2;
                uint32_t a0, a1, a2, a3, l0, l1, l2, l3;
                LDSM4(a0, a1, a2, a3, ka);
                LDSM4(l0, l1, l2, l3, ka + 64);
                MMA(c[mi][0][0], c[mi][0][1], c[mi][0][2], c[mi][0][3], a0, a1, a2, a3, bh0, bh1);
                MMA(c[mi][1][0], c[mi][1][1], c[mi][1][2], c[mi][1][3], a0, a1, a2, a3, bh2, bh3);
                MMA(c[mi][0][0], c[mi][0][1], c[mi][0][2], c[mi][0][3], l0, l1, l2, l3, bh0, bh1);
                MMA(c[mi][1][0], c[mi][1][1], c[mi][1][2], c[mi][1][3], l0, l1, l2, l3, bh2, bh3);
                MMA(c[mi][0][0], c[mi][0][1], c[mi][0][2], c[mi][0][3], a0, a1, a2, a3, bl0, bl1);
                MMA(c[mi][1][0], c[mi][1][1], c[mi][1][2], c[mi][1][3], a0, a1, a2, a3, bl2, bl3);
            }
        }

        // ---- in-register gate epilogue ----
#pragma unroll
        for (int mi = 0; mi < 2; mi++)
#pragma unroll
            for (int ni = 0; ni < 2; ni++) {
                int col0 = 16 * wn + 8 * ni + 2 * tg;
#pragma unroll
                for (int e = 0; e < 4; e++) {
                    int ee = e & 1;
                    float cc = c[mi][ni][e];
                    float gg = fmaf(0.5f, tanha(0.5f * (cc + bgv[ni][ee])), 0.5f);
                    float hh = tanha(cc + buv[ni][ee]);
                    float hn = fmaf(gg, H[mi][ni][e] - sz, fmaf(sn, hh, sz));
                    H[mi][ni][e] = (col0 + ee < DH) ? hn : 0.f;
                }
            }

        __syncthreads();   // all warps done reading A

        // ---- write H (bf16 hi/lo) back into A, plus prefetched x ----
#pragma unroll
        for (int mi = 0; mi < 2; mi++) {
            int r0 = 32 * wm + 16 * mi + g;
#pragma unroll
            for (int ni = 0; ni < 2; ni++) {
                int col0 = 16 * wn + 8 * ni + 2 * tg;
                uint32_t lo0, lo1;
                uint32_t hi0 = bfsplit(H[mi][ni][0], H[mi][ni][1], lo0);
                uint32_t hi1 = bfsplit(H[mi][ni][2], H[mi][ni][3], lo1);
                char* p0 = (char*)As + (r0 * A_LD + col0) * 2;
                char* p1 = (char*)As + ((r0 + 8) * A_LD + col0) * 2;
                *(uint32_t*)p0 = hi0;  *(uint32_t*)(p0 + 224) = lo0;
                *(uint32_t*)p1 = hi1;  *(uint32_t*)(p1 + 224) = lo1;
            }
        }
        if (hx) {
            *(uint4*)((char*)As + (tid >> 3) * (A_LD * 2) + 448 + (tid & 7) * 16) = xp0;
            if (tid < 64) {
                int i = tid + NTHR;
                *(uint4*)((char*)As + (i >> 3) * (A_LD * 2) + 448 + (i & 7) * 16) = xp1;
            }
        }
        __syncthreads();
    }

    // ---- scores ----
    for (int i = tid; i < MROWS * NCLS; i += NTHR) scr[i] = 0.f;
    __syncthreads();
#pragma unroll
    for (int mi = 0; mi < 2; mi++)
#pragma unroll
        for (int half = 0; half < 2; half++) {
            int row = 32 * wm + 16 * mi + g + 8 * half;
            float s[NCLS];
#pragma unroll
            for (int cix = 0; cix < NCLS; cix++) s[cix] = 0.f;
#pragma unroll
            for (int ni = 0; ni < 2; ni++)
#pragma unroll
                for (int e = 0; e < 2; e++) {
                    int col = 16 * wn + 8 * ni + 2 * tg + e;
                    if (col < DH) {
                        float hv = H[mi][ni][2 * half + e];
#pragma unroll
                        for (int cix = 0; cix < NCLS; cix++)
                            s[cix] = fmaf(hv, __ldg(FC + col * NCLS + cix), s[cix]);
                    }
                }
#pragma unroll
            for (int cix = 0; cix < NCLS; cix++)
                atomicAdd(&scr[row * NCLS + cix], s[cix]);
        }
    __syncthreads();
    if (tid < MROWS) {
        int grow = blk * MROWS + tid;
#pragma unroll
        for (int cix = 0; cix < NCLS; cix++)
            out[(size_t)grow * NCLS + cix] = scr[tid * NCLS + cix] + __ldg(FCb + cix);
    }
}

// ---------------- launch ----------------
extern "C" void kernel_launch(void* const* d_in, const int* in_sizes, int n_in,
                              void* d_out, int out_size) {
    const float* x    = (const float*)d_in[0];
    const float* W1   = (const float*)d_in[1];
    const float* W2   = (const float*)d_in[2];
    const float* U1   = (const float*)d_in[3];
    const float* U2   = (const float*)d_in[4];
    const float* bg   = (const float*)d_in[5];
    const float* bu   = (const float*)d_in[6];
    const float* zeta = (const float*)d_in[7];
    const float* nu   = (const float*)d_in[8];
    const float* FC   = (const float*)d_in[9];
    const float* FCb  = (const float*)d_in[10];
    float* out = (float*)d_out;

    cudaFuncSetAttribute(grnn_kernel, cudaFuncAttributeMaxDynamicSharedMemorySize, SM_TOT);

    setup_w<<<16, 256>>>(W1, W2, U1, U2, bg, bu, zeta, nu);
    setup_x<<<(NBLK * TSTEPS * MROWS) / 256, 256>>>(x);
    grnn_kernel<<<NBLK, NTHR, SM_TOT>>>(FC, FCb, out);
}

// round 13
// speedup vs baseline: 1.5273x; 1.0257x over previous
#include <cuda_runtime.h>
#include <cuda_bf16.h>
#include <math.h>
#include <stdint.h>

// ---------------- problem constants ----------------
#define BATCH   8192
#define TSTEPS  99
#define DIN     32
#define DH      100
#define RW      16
#define RU      25
#define NCLS    6
#define MROWS   64
#define NBLK    (BATCH / MROWS)      // 128
#define NTHR    448                  // 14 warps: 2(m) x 7(n)

// A: 64 x 296 bf16. cols: 0-111 Hhi, 112-223 Hlo, 224-255 xhi, 256-287 xlo
#define A_LD    296
#define A_BYTES (64 * A_LD * 2)      // 37888
// B: 288 x 136 bf16. rows: 0-111 Uhi, 112-223 Ulo, 224-255 Whi, 256-287 Wlo
#define B_LD    136
#define B_BYTES (288 * B_LD * 2)     // 78336

#define SM_A    0                    // double buffered: A[0], A[1]
#define SM_B    (SM_A + 2 * A_BYTES)
#define SM_BB   (SM_B + B_BYTES)
#define SM_SCR  (SM_BB + 1024)
#define SM_TOT  (SM_SCR + 1536)      // 156672 B

// ---------------- device-global prepped data ----------------
__device__ __align__(16) __nv_bfloat16 g_Bs[288 * B_LD];
__device__ float g_bb[224];
__device__ float g_sc[2];
__device__ __align__(16) __nv_bfloat16 g_AXB[(size_t)NBLK * TSTEPS * 4096];

__device__ __forceinline__ float tanha(float v) {
    float r; asm("tanh.approx.f32 %0, %1;" : "=f"(r) : "f"(v)); return r;
}
__device__ __forceinline__ uint32_t pk2(__nv_bfloat16 a, __nv_bfloat16 b) {
    return (uint32_t)__bfloat16_as_ushort(a) | ((uint32_t)__bfloat16_as_ushort(b) << 16);
}
__device__ __forceinline__ uint32_t bfsplit(float v0, float v1, uint32_t& lo) {
    __nv_bfloat16 h0 = __float2bfloat16_rn(v0);
    __nv_bfloat16 h1 = __float2bfloat16_rn(v1);
    lo = pk2(__float2bfloat16_rn(v0 - __bfloat162float(h0)),
             __float2bfloat16_rn(v1 - __bfloat162float(h1)));
    return pk2(h0, h1);
}

#define LDSM4(r0,r1,r2,r3,a) \
    asm volatile("ldmatrix.sync.aligned.m8n8.x4.shared.b16 {%0,%1,%2,%3}, [%4];" \
                 : "=r"(r0),"=r"(r1),"=r"(r2),"=r"(r3) : "r"(a))
#define LDSM4T(r0,r1,r2,r3,a) \
    asm volatile("ldmatrix.sync.aligned.m8n8.x4.trans.shared.b16 {%0,%1,%2,%3}, [%4];" \
                 : "=r"(r0),"=r"(r1),"=r"(r2),"=r"(r3) : "r"(a))
#define MMA(c0,c1,c2,c3,a0,a1,a2,a3,b0,b1) \
    asm volatile("mma.sync.aligned.m16n8k16.row.col.f32.bf16.bf16.f32 " \
                 "{%0,%1,%2,%3}, {%4,%5,%6,%7}, {%8,%9}, {%0,%1,%2,%3};" \
                 : "+f"(c0),"+f"(c1),"+f"(c2),"+f"(c3) \
                 : "r"(a0),"r"(a1),"r"(a2),"r"(a3),"r"(b0),"r"(b1))

// ---------------- setup 1: weights -> split B image (verbatim) ----------------
__global__ void setup_w(const float* __restrict__ W1, const float* __restrict__ W2,
                        const float* __restrict__ U1, const float* __restrict__ U2,
                        const float* __restrict__ bg, const float* __restrict__ bu,
                        const float* __restrict__ zeta, const float* __restrict__ nu) {
    int tid = blockIdx.x * blockDim.x + threadIdx.x;
    int nth = gridDim.x * blockDim.x;
    for (int idx = tid; idx < 288 * B_LD; idx += nth) {
        int k = idx / B_LD, n = idx % B_LD;
        float v = 0.f;
        bool lo = false;
        if (n < DH) {
            if (k < 112) {
                if (k < DH)
                    for (int r = 0; r < RU; r++) v = fmaf(U1[k * RU + r], U2[r * DH + n], v);
            } else if (k < 224) {
                int kk = k - 112; lo = true;
                if (kk < DH)
                    for (int r = 0; r < RU; r++) v = fmaf(U1[kk * RU + r], U2[r * DH + n], v);
            } else if (k < 256) {
                int kk = k - 224;
                for (int r = 0; r < RW; r++) v = fmaf(W1[kk * RW + r], W2[r * DH + n], v);
            } else {
                int kk = k - 256; lo = true;
                for (int r = 0; r < RW; r++) v = fmaf(W1[kk * RW + r], W2[r * DH + n], v);
            }
        }
        __nv_bfloat16 hi = __float2bfloat16_rn(v);
        g_Bs[idx] = lo ? __float2bfloat16_rn(v - __bfloat162float(hi)) : hi;
    }
    for (int j = tid; j < 112; j += nth) {
        g_bb[2 * j]     = (j < DH) ? bg[j] : 0.f;
        g_bb[2 * j + 1] = (j < DH) ? bu[j] : 0.f;
    }
    if (tid == 0) {
        g_sc[0] = 1.f / (1.f + expf(-zeta[0]));
        g_sc[1] = 1.f / (1.f + expf(-nu[0]));
    }
}

// ---------------- setup 2: x -> split hi/lo row images (verbatim) ----------------
__global__ void __launch_bounds__(256)
setup_x(const float* __restrict__ x) {
    int gid = blockIdx.x * 256 + threadIdx.x;
    int blk = gid / (TSTEPS * MROWS);
    int rem = gid % (TSTEPS * MROWS);
    int t = rem / MROWS, r = rem % MROWS;
    const float* xr = x + (size_t)(blk * MROWS + r) * (TSTEPS * DIN) + t * DIN;
    __nv_bfloat16 buf[64];
#pragma unroll
    for (int k = 0; k < DIN; k++) {
        float v = xr[k];
        __nv_bfloat16 hi = __float2bfloat16_rn(v);
        buf[k]      = hi;
        buf[32 + k] = __float2bfloat16_rn(v - __bfloat162float(hi));
    }
    uint4* dst = (uint4*)(g_AXB + ((size_t)(blk * TSTEPS + t)) * 4096 + r * 64);
    const uint4* src = (const uint4*)buf;
#pragma unroll
    for (int i = 0; i < 8; i++) dst[i] = src[i];
}

// ---------------- persistent raw-MMA recurrent kernel ----------------
__global__ void __launch_bounds__(NTHR)
grnn_kernel(const float* __restrict__ FC, const float* __restrict__ FCb,
            float* __restrict__ out) {
    extern __shared__ __align__(16) char sm[];
    __nv_bfloat16* As = (__nv_bfloat16*)(sm + SM_A);     // double buffered
    __nv_bfloat16* Bs = (__nv_bfloat16*)(sm + SM_B);
    float2* bbs = (float2*)(sm + SM_BB);
    float*  scr = (float*)(sm + SM_SCR);

    const int tid = threadIdx.x;
    const int blk = blockIdx.x;

    // ---- init: B copy, A[0] zero + x(0), biases ----
    {
        uint4* d = (uint4*)Bs; const uint4* s = (const uint4*)g_Bs;
        for (int i = tid; i < B_BYTES / 16; i += NTHR) d[i] = s[i];
        d = (uint4*)As;
        for (int i = tid; i < A_BYTES / 16; i += NTHR) d[i] = make_uint4(0, 0, 0, 0);
        const uint4* xs0 = (const uint4*)(g_AXB + (size_t)blk * TSTEPS * 4096);
        for (int i = tid; i < 512; i += NTHR)
            *(uint4*)((char*)As + (i >> 3) * (A_LD * 2) + 448 + (i & 7) * 16) = xs0[i];
        for (int j = tid; j < 112; j += NTHR)
            bbs[j] = make_float2(g_bb[2 * j], g_bb[2 * j + 1]);
    }
    __syncthreads();

    const float sz = g_sc[0];
    const float sn = g_sc[1];

    const int w    = tid >> 5;
    const int lane = tid & 31;
    const int wm   = w & 1;
    const int wn   = w >> 1;
    const int g    = lane >> 2;
    const int tg   = lane & 3;
    const int lm   = lane >> 3;
    const int lr   = lane & 7;

    uint32_t As32 = (uint32_t)__cvta_generic_to_shared(As);
    uint32_t Bs32 = (uint32_t)__cvta_generic_to_shared(Bs);
    const uint32_t aLane = (uint32_t)(((32 * wm + lr + ((lm & 1) << 3)) * A_LD + ((lm >> 1) << 3)) * 2);
    const uint32_t bAddr = Bs32 + (uint32_t)(((lr + ((lm & 1) << 3)) * B_LD + 16 * wn + ((lm >> 1) << 3)) * 2);

    // ---- hoist ALL B fragments into registers (constant across steps) ----
    uint32_t BH[7][8], BX[2][8];
#pragma unroll
    for (int kk = 0; kk < 7; kk++) {
        uint32_t kb = bAddr + kk * 16 * B_LD * 2;
        LDSM4T(BH[kk][0], BH[kk][1], BH[kk][2], BH[kk][3], kb);
        LDSM4T(BH[kk][4], BH[kk][5], BH[kk][6], BH[kk][7], kb + 112 * B_LD * 2);
    }
#pragma unroll
    for (int kk = 0; kk < 2; kk++) {
        uint32_t kb = bAddr + (224 + 16 * kk) * B_LD * 2;
        LDSM4T(BX[kk][0], BX[kk][1], BX[kk][2], BX[kk][3], kb);
        LDSM4T(BX[kk][4], BX[kk][5], BX[kk][6], BX[kk][7], kb + 32 * B_LD * 2);
    }

    // biases
    float bgv[2][2], buv[2][2];
#pragma unroll
    for (int ni = 0; ni < 2; ni++)
#pragma unroll
        for (int e = 0; e < 2; e++) {
            float2 bb = bbs[16 * wn + 8 * ni + 2 * tg + e];
            bgv[ni][e] = bb.x; buv[ni][e] = bb.y;
        }

    float H[2][2][4];
#pragma unroll
    for (int mi = 0; mi < 2; mi++)
#pragma unroll
        for (int ni = 0; ni < 2; ni++)
#pragma unroll
            for (int e = 0; e < 4; e++) H[mi][ni][e] = 0.f;

    int p = 0;
    for (int t = 0; t < TSTEPS; t++) {
        // prefetch next step's x rows
        uint4 xp0, xp1;
        const int hx = (t + 1 < TSTEPS);
        if (hx) {
            const uint4* s = (const uint4*)(g_AXB + (size_t)(blk * TSTEPS + t + 1) * 4096);
            xp0 = s[tid];
            if (tid < 64) xp1 = s[tid + NTHR];
        }

        const uint32_t aAddr0 = As32 + p * A_BYTES + aLane;
        const uint32_t aAddr1 = aAddr0 + 16 * A_LD * 2;

        float c[2][2][4];
#pragma unroll
        for (int mi = 0; mi < 2; mi++)
#pragma unroll
            for (int ni = 0; ni < 2; ni++)
#pragma unroll
                for (int e = 0; e < 4; e++) c[mi][ni][e] = 0.f;

        // ---- H part: 7 k-units ----
#pragma unroll
        for (int kk = 0; kk < 7; kk++) {
#pragma unroll
            for (int mi = 0; mi < 2; mi++) {
                uint32_t ka = (mi ? aAddr1 : aAddr0) + kk * 32;
                uint32_t a0, a1, a2, a3, l0, l1, l2, l3;
                LDSM4(a0, a1, a2, a3, ka);
                LDSM4(l0, l1, l2, l3, ka + 224);
                MMA(c[mi][0][0], c[mi][0][1], c[mi][0][2], c[mi][0][3], a0, a1, a2, a3, BH[kk][0], BH[kk][1]);
                MMA(c[mi][1][0], c[mi][1][1], c[mi][1][2], c[mi][1][3], a0, a1, a2, a3, BH[kk][2], BH[kk][3]);
                MMA(c[mi][0][0], c[mi][0][1], c[mi][0][2], c[mi][0][3], l0, l1, l2, l3, BH[kk][0], BH[kk][1]);
                MMA(c[mi][1][0], c[mi][1][1], c[mi][1][2], c[mi][1][3], l0, l1, l2, l3, BH[kk][2], BH[kk][3]);
                MMA(c[mi][0][0], c[mi][0][1], c[mi][0][2], c[mi][0][3], a0, a1, a2, a3, BH[kk][4], BH[kk][5]);
                MMA(c[mi][1][0], c[mi][1][1], c[mi][1][2], c[mi][1][3], a0, a1, a2, a3, BH[kk][6], BH[kk][7]);
            }
        }
        // ---- x part: 2 k-units ----
#pragma unroll
        for (int kk = 0; kk < 2; kk++) {
#pragma unroll
            for (int mi = 0; mi < 2; mi++) {
                uint32_t ka = (mi ? aAddr1 : aAddr0) + (224 + 16 * kk) * 2;
                uint32_t a0, a1, a2, a3, l0, l1, l2, l3;
                LDSM4(a0, a1, a2, a3, ka);
                LDSM4(l0, l1, l2, l3, ka + 64);
                MMA(c[mi][0][0], c[mi][0][1], c[mi][0][2], c[mi][0][3], a0, a1, a2, a3, BX[kk][0], BX[kk][1]);
                MMA(c[mi][1][0], c[mi][1][1], c[mi][1][2], c[mi][1][3], a0, a1, a2, a3, BX[kk][2], BX[kk][3]);
                MMA(c[mi][0][0], c[mi][0][1], c[mi][0][2], c[mi][0][3], l0, l1, l2, l3, BX[kk][0], BX[kk][1]);
                MMA(c[mi][1][0], c[mi][1][1], c[mi][1][2], c[mi][1][3], l0, l1, l2, l3, BX[kk][2], BX[kk][3]);
                MMA(c[mi][0][0], c[mi][0][1], c[mi][0][2], c[mi][0][3], a0, a1, a2, a3, BX[kk][4], BX[kk][5]);
                MMA(c[mi][1][0], c[mi][1][1], c[mi][1][2], c[mi][1][3], a0, a1, a2, a3, BX[kk][6], BX[kk][7]);
            }
        }

        // ---- in-register gate epilogue ----
#pragma unroll
        for (int mi = 0; mi < 2; mi++)
#pragma unroll
            for (int ni = 0; ni < 2; ni++) {
                int col0 = 16 * wn + 8 * ni + 2 * tg;
#pragma unroll
                for (int e = 0; e < 4; e++) {
                    int ee = e & 1;
                    float cc = c[mi][ni][e];
                    float gg = fmaf(0.5f, tanha(0.5f * (cc + bgv[ni][ee])), 0.5f);
                    float hh = tanha(cc + buv[ni][ee]);
                    float hn = fmaf(gg, H[mi][ni][e] - sz, fmaf(sn, hh, sz));
                    H[mi][ni][e] = (col0 + ee < DH) ? hn : 0.f;
                }
            }

        // ---- write H + x into the OTHER buffer (no barrier needed before) ----
        char* Aw = (char*)As + (p ^ 1) * A_BYTES;
#pragma unroll
        for (int mi = 0; mi < 2; mi++) {
            int r0 = 32 * wm + 16 * mi + g;
#pragma unroll
            for (int ni = 0; ni < 2; ni++) {
                int col0 = 16 * wn + 8 * ni + 2 * tg;
                uint32_t lo0, lo1;
                uint32_t hi0 = bfsplit(H[mi][ni][0], H[mi][ni][1], lo0);
                uint32_t hi1 = bfsplit(H[mi][ni][2], H[mi][ni][3], lo1);
                char* p0 = Aw + (r0 * A_LD + col0) * 2;
                char* p1 = Aw + ((r0 + 8) * A_LD + col0) * 2;
                *(uint32_t*)p0 = hi0;  *(uint32_t*)(p0 + 224) = lo0;
                *(uint32_t*)p1 = hi1;  *(uint32_t*)(p1 + 224) = lo1;
            }
        }
        if (hx) {
            *(uint4*)(Aw + (tid >> 3) * (A_LD * 2) + 448 + (tid & 7) * 16) = xp0;
            if (tid < 64) {
                int i = tid + NTHR;
                *(uint4*)(Aw + (i >> 3) * (A_LD * 2) + 448 + (i & 7) * 16) = xp1;
            }
        }
        __syncthreads();
        p ^= 1;
    }

    // ---- scores ----
    for (int i = tid; i < MROWS * NCLS; i += NTHR) scr[i] = 0.f;
    __syncthreads();
#pragma unroll
    for (int mi = 0; mi < 2; mi++)
#pragma unroll
        for (int half = 0; half < 2; half++) {
            int row = 32 * wm + 16 * mi + g + 8 * half;
            float s[NCLS];
#pragma unroll
            for (int cix = 0; cix < NCLS; cix++) s[cix] = 0.f;
#pragma unroll
            for (int ni = 0; ni < 2; ni++)
#pragma unroll
                for (int e = 0; e < 2; e++) {
                    int col = 16 * wn + 8 * ni + 2 * tg + e;
                    if (col < DH) {
                        float hv = H[mi][ni][2 * half + e];
#pragma unroll
                        for (int cix = 0; cix < NCLS; cix++)
                            s[cix] = fmaf(hv, __ldg(FC + col * NCLS + cix), s[cix]);
                    }
                }
#pragma unroll
            for (int cix = 0; cix < NCLS; cix++)
                atomicAdd(&scr[row * NCLS + cix], s[cix]);
        }
    __syncthreads();
    if (tid < MROWS) {
        int grow = blk * MROWS + tid;
#pragma unroll
        for (int cix = 0; cix < NCLS; cix++)
            out[(size_t)grow * NCLS + cix] = scr[tid * NCLS + cix] + __ldg(FCb + cix);
    }
}

// ---------------- launch ----------------
extern "C" void kernel_launch(void* const* d_in, const int* in_sizes, int n_in,
                              void* d_out, int out_size) {
    const float* x    = (const float*)d_in[0];
    const float* W1   = (const float*)d_in[1];
    const float* W2   = (const float*)d_in[2];
    const float* U1   = (const float*)d_in[3];
    const float* U2   = (const float*)d_in[4];
    const float* bg   = (const float*)d_in[5];
    const float* bu   = (const float*)d_in[6];
    const float* zeta = (const float*)d_in[7];
    const float* nu   = (const float*)d_in[8];
    const float* FC   = (const float*)d_in[9];
    const float* FCb  = (const float*)d_in[10];
    float* out = (float*)d_out;

    cudaFuncSetAttribute(grnn_kernel, cudaFuncAttributeMaxDynamicSharedMemorySize, SM_TOT);

    setup_w<<<16, 256>>>(W1, W2, U1, U2, bg, bu, zeta, nu);
    setup_x<<<(NBLK * TSTEPS * MROWS) / 256, 256>>>(x);
    grnn_kernel<<<NBLK, NTHR, SM_TOT>>>(FC, FCb, out);
}